// round 2
// baseline (speedup 1.0000x reference)
#include <cuda_runtime.h>

// x:(8,8,512,64) f32, a:(64,1) f32 -> out:(8,512,512) f32
// S[n,i,j] = E[n,i,j] / sum_i' E[n,i',j],  E = exp(relu(sum_f a[f]*|xm[n,i,f]-xm[n,j,f]|))
// xm = x[:, 4, :, :]

#define VV 512
#define FF 64
#define JT 32          // j-tile per block
#define XI_STRIDE 68   // float4-aligned padded rows (68%32==4 -> conflict-free)
#define XJ_STRIDE 68   // must be mult of 4 for LDS.128; bank step 4 -> conflict-free
#define THREADS 512

// smem floats: sxi 512*68 + sxj 32*68 + sa 64 + red 2048 + sinv 32
#define SMEM_FLOATS (VV*XI_STRIDE + JT*XJ_STRIDE + FF + 64*JT + JT)

__global__ __launch_bounds__(THREADS) void graph_learn_kernel(
    const float* __restrict__ x, const float* __restrict__ a,
    float* __restrict__ out)
{
    extern __shared__ float smem[];
    float* sxi  = smem;
    float* sxj  = sxi + VV * XI_STRIDE;
    float* sa   = sxj + JT * XJ_STRIDE;
    float* red  = sa + FF;
    float* sinv = red + 64 * JT;

    const int n   = blockIdx.y;
    const int j0  = blockIdx.x * JT;
    const int tid = threadIdx.x;

    const float* xm = x + ((size_t)(n * 8 + 4)) * VV * FF;

    // ---- stage xm[n] (512 rows) into padded smem ----
    const float4* xg = (const float4*)xm;
    #pragma unroll
    for (int k = 0; k < (VV * FF / 4) / THREADS; k++) {      // 16 iters
        int g   = tid + k * THREADS;
        int row = g >> 4, f4 = g & 15;
        float4 v = xg[g];
        *(float4*)(sxi + row * XI_STRIDE + f4 * 4) = v;
    }
    // ---- stage 32-row j-tile ----
    const float4* xjg = (const float4*)(xm + (size_t)j0 * FF);
    if (tid < JT * FF / 4) {
        int row = tid >> 4, f4 = tid & 15;
        float4 v = xjg[tid];
        *(float4*)(sxj + row * XJ_STRIDE + f4 * 4) = v;
    }
    if (tid < FF) sa[tid] = a[tid];
    __syncthreads();

    const int tx = tid & 7;    // 8 groups of 4 j
    const int ty = tid >> 3;   // 0..63, each owns 8 i strided by 64

    float acc[8][4];
    #pragma unroll
    for (int r = 0; r < 8; r++)
        #pragma unroll
        for (int c = 0; c < 4; c++) acc[r][c] = 0.f;

    const float* bj = sxj + (tx * 4) * XJ_STRIDE;
    const float* ai = sxi + ty * XI_STRIDE;

    #pragma unroll 2
    for (int q = 0; q < FF / 4; q++) {                       // 16 f-chunks
        const float4 av = *(const float4*)(sa + q * 4);
        float4 B[4];
        #pragma unroll
        for (int c = 0; c < 4; c++)
            B[c] = *(const float4*)(bj + c * XJ_STRIDE + q * 4);

        #pragma unroll
        for (int r = 0; r < 8; r++) {
            const float4 A = *(const float4*)(ai + r * 64 * XI_STRIDE + q * 4);
            #pragma unroll
            for (int c = 0; c < 4; c++) {
                float s;
                s  = av.x * fabsf(A.x - B[c].x);
                s += av.y * fabsf(A.y - B[c].y);
                s += av.z * fabsf(A.z - B[c].z);
                s += av.w * fabsf(A.w - B[c].w);
                acc[r][c] += s;
            }
        }
    }

    // ---- exp(relu) + per-thread partial column sums ----
    float psum[4] = {0.f, 0.f, 0.f, 0.f};
    #pragma unroll
    for (int r = 0; r < 8; r++)
        #pragma unroll
        for (int c = 0; c < 4; c++) {
            float e = __expf(fmaxf(acc[r][c], 0.f));
            acc[r][c] = e;
            psum[c] += e;
        }
    #pragma unroll
    for (int c = 0; c < 4; c++) red[ty * JT + tx * 4 + c] = psum[c];
    __syncthreads();

    if (tid < JT) {
        float s = 0.f;
        #pragma unroll
        for (int t = 0; t < 64; t++) s += red[t * JT + tid];
        sinv[tid] = 1.0f / s;
    }
    __syncthreads();

    const float inv0 = sinv[tx * 4 + 0];
    const float inv1 = sinv[tx * 4 + 1];
    const float inv2 = sinv[tx * 4 + 2];
    const float inv3 = sinv[tx * 4 + 3];

    float* outn = out + (size_t)n * VV * VV + j0;
    #pragma unroll
    for (int r = 0; r < 8; r++) {
        int i = r * 64 + ty;
        float4 v;
        v.x = acc[r][0] * inv0;
        v.y = acc[r][1] * inv1;
        v.z = acc[r][2] * inv2;
        v.w = acc[r][3] * inv3;
        *(float4*)(outn + (size_t)i * VV + tx * 4) = v;
    }
}

extern "C" void kernel_launch(void* const* d_in, const int* in_sizes, int n_in,
                              void* d_out, int out_size)
{
    const float* x = (const float*)d_in[0];
    const float* a = (const float*)d_in[1];
    float* out     = (float*)d_out;

    const size_t smem_bytes = (size_t)SMEM_FLOATS * sizeof(float);
    cudaFuncSetAttribute(graph_learn_kernel,
                         cudaFuncAttributeMaxDynamicSharedMemorySize,
                         (int)smem_bytes);

    dim3 grid(VV / JT, 8);   // 128 blocks
    graph_learn_kernel<<<grid, THREADS, smem_bytes>>>(x, a, out);
}

// round 3
// speedup vs baseline: 1.0055x; 1.0055x over previous
#include <cuda_runtime.h>

// x:(8,8,512,64) f32, a:(64,1) f32 -> out:(8,512,512) f32
// S[n,i,j] = E[n,i,j] / sum_i' E[n,i',j],  E = exp(relu(sum_f a[f]*|xm[n,i,f]-xm[n,j,f]|))
// xm = x[:, 4, :, :]

#define VV 512
#define FF 64
#define JT 32          // j-tile per block
#define XI_STRIDE 68   // float4-aligned padded rows (68%32==4 -> conflict-free)
#define XJ_STRIDE 68   // must be mult of 4 for LDS.128; bank step 4 -> conflict-free
#define THREADS 512

// smem floats: sxi 512*68 + sxj 32*68 + sa 64 + red 2048 + sinv 32
#define SMEM_FLOATS (VV*XI_STRIDE + JT*XJ_STRIDE + FF + 64*JT + JT)

__global__ __launch_bounds__(THREADS) void graph_learn_kernel(
    const float* __restrict__ x, const float* __restrict__ a,
    float* __restrict__ out)
{
    extern __shared__ float smem[];
    float* sxi  = smem;
    float* sxj  = sxi + VV * XI_STRIDE;
    float* sa   = sxj + JT * XJ_STRIDE;
    float* red  = sa + FF;
    float* sinv = red + 64 * JT;

    const int n   = blockIdx.y;
    const int j0  = blockIdx.x * JT;
    const int tid = threadIdx.x;

    const float* xm = x + ((size_t)(n * 8 + 4)) * VV * FF;

    // ---- stage xm[n] (512 rows) into padded smem ----
    const float4* xg = (const float4*)xm;
    #pragma unroll
    for (int k = 0; k < (VV * FF / 4) / THREADS; k++) {      // 16 iters
        int g   = tid + k * THREADS;
        int row = g >> 4, f4 = g & 15;
        float4 v = xg[g];
        *(float4*)(sxi + row * XI_STRIDE + f4 * 4) = v;
    }
    // ---- stage 32-row j-tile ----
    const float4* xjg = (const float4*)(xm + (size_t)j0 * FF);
    if (tid < JT * FF / 4) {
        int row = tid >> 4, f4 = tid & 15;
        float4 v = xjg[tid];
        *(float4*)(sxj + row * XJ_STRIDE + f4 * 4) = v;
    }
    if (tid < FF) sa[tid] = a[tid];
    __syncthreads();

    const int tx = tid & 7;    // 8 groups of 4 j
    const int ty = tid >> 3;   // 0..63, each owns 8 i strided by 64

    float acc[8][4];
    #pragma unroll
    for (int r = 0; r < 8; r++)
        #pragma unroll
        for (int c = 0; c < 4; c++) acc[r][c] = 0.f;

    const float* bj = sxj + (tx * 4) * XJ_STRIDE;
    const float* ai = sxi + ty * XI_STRIDE;

    #pragma unroll 2
    for (int q = 0; q < FF / 4; q++) {                       // 16 f-chunks
        const float4 av = *(const float4*)(sa + q * 4);
        float4 B[4];
        #pragma unroll
        for (int c = 0; c < 4; c++)
            B[c] = *(const float4*)(bj + c * XJ_STRIDE + q * 4);

        #pragma unroll
        for (int r = 0; r < 8; r++) {
            const float4 A = *(const float4*)(ai + r * 64 * XI_STRIDE + q * 4);
            #pragma unroll
            for (int c = 0; c < 4; c++) {
                float s;
                s  = av.x * fabsf(A.x - B[c].x);
                s += av.y * fabsf(A.y - B[c].y);
                s += av.z * fabsf(A.z - B[c].z);
                s += av.w * fabsf(A.w - B[c].w);
                acc[r][c] += s;
            }
        }
    }

    // ---- exp(relu) + per-thread partial column sums ----
    float psum[4] = {0.f, 0.f, 0.f, 0.f};
    #pragma unroll
    for (int r = 0; r < 8; r++)
        #pragma unroll
        for (int c = 0; c < 4; c++) {
            float e = __expf(fmaxf(acc[r][c], 0.f));
            acc[r][c] = e;
            psum[c] += e;
        }
    #pragma unroll
    for (int c = 0; c < 4; c++) red[ty * JT + tx * 4 + c] = psum[c];
    __syncthreads();

    if (tid < JT) {
        float s = 0.f;
        #pragma unroll
        for (int t = 0; t < 64; t++) s += red[t * JT + tid];
        sinv[tid] = 1.0f / s;
    }
    __syncthreads();

    const float inv0 = sinv[tx * 4 + 0];
    const float inv1 = sinv[tx * 4 + 1];
    const float inv2 = sinv[tx * 4 + 2];
    const float inv3 = sinv[tx * 4 + 3];

    float* outn = out + (size_t)n * VV * VV + j0;
    #pragma unroll
    for (int r = 0; r < 8; r++) {
        int i = r * 64 + ty;
        float4 v;
        v.x = acc[r][0] * inv0;
        v.y = acc[r][1] * inv1;
        v.z = acc[r][2] * inv2;
        v.w = acc[r][3] * inv3;
        *(float4*)(outn + (size_t)i * VV + tx * 4) = v;
    }
}

extern "C" void kernel_launch(void* const* d_in, const int* in_sizes, int n_in,
                              void* d_out, int out_size)
{
    const float* x = (const float*)d_in[0];
    const float* a = (const float*)d_in[1];
    float* out     = (float*)d_out;

    const size_t smem_bytes = (size_t)SMEM_FLOATS * sizeof(float);
    cudaFuncSetAttribute(graph_learn_kernel,
                         cudaFuncAttributeMaxDynamicSharedMemorySize,
                         (int)smem_bytes);

    dim3 grid(VV / JT, 8);   // 128 blocks
    graph_learn_kernel<<<grid, THREADS, smem_bytes>>>(x, a, out);
}